// round 5
// baseline (speedup 1.0000x reference)
#include <cuda_runtime.h>
#include <cuda_bf16.h>
#include <math.h>
#include <stdint.h>

#define NCONF 8192
#define NT 64
#define NX 64

// -------- dynamic smem layout (bytes) --------
// A: [128 rows (cfg*64+t)][64 bf16 = 128B], swizzled chunk^=(row&7)
// B: [64 rows (v)][64 bf16 = 128B], swizzled
#define SM_A_HI   0        // 16384
#define SM_A_LO   16384    // 16384
#define SM_B_HI   32768    //  8192
#define SM_B_LO   40960    //  8192
#define SM_BIAS   49152    //  256 (64 f32)
#define SM_T0     49408    //  8 (2 ints)
#define SM_TOTAL  49536

static __device__ __forceinline__ uint32_t smem_u32(const void* p) {
    uint32_t a;
    asm("{ .reg .u64 t; cvta.to.shared.u64 t, %1; cvt.u32.u64 %0, t; }" : "=r"(a) : "l"(p));
    return a;
}

static __device__ __forceinline__ void ldsm_x4(uint32_t& r0, uint32_t& r1,
                                               uint32_t& r2, uint32_t& r3, uint32_t addr) {
    asm volatile("ldmatrix.sync.aligned.m8n8.x4.shared.b16 {%0,%1,%2,%3}, [%4];"
                 : "=r"(r0), "=r"(r1), "=r"(r2), "=r"(r3) : "r"(addr));
}
static __device__ __forceinline__ void ldsm_x4t(uint32_t& r0, uint32_t& r1,
                                                uint32_t& r2, uint32_t& r3, uint32_t addr) {
    asm volatile("ldmatrix.sync.aligned.m8n8.x4.trans.shared.b16 {%0,%1,%2,%3}, [%4];"
                 : "=r"(r0), "=r"(r1), "=r"(r2), "=r"(r3) : "r"(addr));
}
static __device__ __forceinline__ void mma_bf16(float* d, uint32_t a0, uint32_t a1,
                                                uint32_t a2, uint32_t a3,
                                                uint32_t b0, uint32_t b1) {
    asm volatile(
        "mma.sync.aligned.m16n8k16.row.col.f32.bf16.bf16.f32 "
        "{%0,%1,%2,%3}, {%4,%5,%6,%7}, {%8,%9}, {%0,%1,%2,%3};"
        : "+f"(d[0]), "+f"(d[1]), "+f"(d[2]), "+f"(d[3])
        : "r"(a0), "r"(a1), "r"(a2), "r"(a3), "r"(b0), "r"(b1));
}

static __device__ __forceinline__ uint32_t pack_hi(float x, float y) {
    uint32_t lo = (uint32_t)__bfloat16_as_ushort(__float2bfloat16(x));
    uint32_t hi = (uint32_t)__bfloat16_as_ushort(__float2bfloat16(y));
    return lo | (hi << 16);
}
static __device__ __forceinline__ uint32_t pack_lo(float x, float y) {
    float xr = x - __bfloat162float(__float2bfloat16(x));
    float yr = y - __bfloat162float(__float2bfloat16(y));
    return pack_hi(xr, yr);
}

__global__ void __launch_bounds__(128, 4) fused_kernel(
    const float* __restrict__ phi, const float* __restrict__ W,
    const float* __restrict__ b, float* __restrict__ out, int write_logdet)
{
    extern __shared__ char smem[];
    uint32_t sbase = smem_u32(smem);
    int tid  = threadIdx.x;
    int wid  = tid >> 5;
    int lane = tid & 31;

    // ---------------- LU block: log|det W| + logDet tail ----------------
    if (blockIdx.x == NCONF / 2) {
        float (*A)[65] = reinterpret_cast<float(*)[65]>(smem);
        float* m  = reinterpret_cast<float*>(smem + 16640);
        float* rv = reinterpret_cast<float*>(smem + 16896);
        int*   ri = reinterpret_cast<int*>(smem + 16904);
        float* sld = reinterpret_cast<float*>(smem + 16912);

        for (int idx = tid; idx < 64 * 64; idx += 128)
            A[idx >> 6][idx & 63] = W[idx];
        __syncthreads();

        float ld = 0.0f;
        for (int k = 0; k < 64; ++k) {
            if (tid < 64) {
                float v  = (tid >= k) ? fabsf(A[tid][k]) : -1.0f;
                int   vi = tid;
                #pragma unroll
                for (int off = 16; off > 0; off >>= 1) {
                    float ov = __shfl_down_sync(0xffffffffu, v,  off);
                    int   oi = __shfl_down_sync(0xffffffffu, vi, off);
                    if (ov > v) { v = ov; vi = oi; }
                }
                if ((tid & 31) == 0) { rv[tid >> 5] = v; ri[tid >> 5] = vi; }
            }
            __syncthreads();
            int p = (rv[1] > rv[0]) ? ri[1] : ri[0];
            if (tid < 64 && p != k) {
                float t1 = A[k][tid], t2 = A[p][tid];
                A[k][tid] = t2; A[p][tid] = t1;
            }
            __syncthreads();
            float piv = A[k][k];
            if (tid < 64) {
                ld += logf(fabsf(piv));
                if (tid > k) m[tid] = A[tid][k] / piv;
            }
            __syncthreads();
            if (tid < 64 && tid > k) {
                float akj = A[k][tid];
                for (int r = k + 1; r < 64; ++r)
                    A[r][tid] -= m[r] * akj;
            }
            __syncthreads();
        }
        if (write_logdet) {
            if (tid == 0) *sld = ld;
            __syncthreads();
            float val = (float)NT * (*sld);
            float* tail = out + (size_t)NCONF * NT * NX;
            for (int idx = tid; idx < NCONF; idx += 128)
                tail[idx] = val;
        }
        return;
    }

    // ---------------- GEMM block: 2 configs ----------------
    int i0 = blockIdx.x * 2;

    // --- T0 pre-pass: warp c -> T0 for config c (gmem cols 0,1) ---
    if (wid < 2) {
        const float* p = phi + (size_t)(i0 + wid) * (NT * NX);
        float2 v0 = *reinterpret_cast<const float2*>(p + (size_t)lane * NX);
        float2 v1 = *reinterpret_cast<const float2*>(p + (size_t)(lane + 32) * NX);
        float b0 = fabsf(v0.x); int j0 = lane;
        float c0 = fabsf(v1.x);
        if (c0 < b0) { b0 = c0; j0 = lane + 32; }
        float b1 = fabsf(v0.y); int j1 = lane;
        float c1 = fabsf(v1.y);
        if (c1 < b1) { b1 = c1; j1 = lane + 32; }
        #pragma unroll
        for (int off = 16; off > 0; off >>= 1) {
            float ob = __shfl_down_sync(0xffffffffu, b0, off);
            int   oj = __shfl_down_sync(0xffffffffu, j0, off);
            if (ob < b0 || (ob == b0 && oj < j0)) { b0 = ob; j0 = oj; }
            ob = __shfl_down_sync(0xffffffffu, b1, off);
            oj = __shfl_down_sync(0xffffffffu, j1, off);
            if (ob < b1 || (ob == b1 && oj < j1)) { b1 = ob; j1 = oj; }
        }
        if (lane == 0)
            reinterpret_cast<int*>(smem + SM_T0)[wid] = (j0 > j1) ? j1 : j0;
    }
    if (tid >= 64)
        reinterpret_cast<float*>(smem + SM_BIAS)[tid - 64] = b[tid - 64];

    // --- A: phi -> bf16 hi/lo, straight layout + swizzle (uint2 stores) ---
    {
        const float4* g4 = reinterpret_cast<const float4*>(phi + (size_t)i0 * (NT * NX));
        #pragma unroll
        for (int s = 0; s < 16; ++s) {
            int idx = tid + 128 * s;            // 0..2047
            float4 v = g4[idx];
            int mrow = idx >> 4;                // cfg*64 + t
            int q    = idx & 15;                // float4 within row
            uint32_t off = (uint32_t)mrow * 128 +
                           ((uint32_t)((q >> 1) ^ (mrow & 7)) << 4) + ((q & 1) << 3);
            uint2 h = make_uint2(pack_hi(v.x, v.y), pack_hi(v.z, v.w));
            uint2 l = make_uint2(pack_lo(v.x, v.y), pack_lo(v.z, v.w));
            *reinterpret_cast<uint2*>(smem + SM_A_HI + off) = h;
            *reinterpret_cast<uint2*>(smem + SM_A_LO + off) = l;
        }
    }
    // --- B: W -> bf16 hi/lo, straight layout + swizzle ---
    {
        const float4* w4 = reinterpret_cast<const float4*>(W);
        #pragma unroll
        for (int s = 0; s < 8; ++s) {
            int idx = tid + 128 * s;            // 0..1023
            float4 v = w4[idx];
            int vrow = idx >> 4;
            int q    = idx & 15;
            uint32_t off = (uint32_t)vrow * 128 +
                           ((uint32_t)((q >> 1) ^ (vrow & 7)) << 4) + ((q & 1) << 3);
            uint2 h = make_uint2(pack_hi(v.x, v.y), pack_hi(v.z, v.w));
            uint2 l = make_uint2(pack_lo(v.x, v.y), pack_lo(v.z, v.w));
            *reinterpret_cast<uint2*>(smem + SM_B_HI + off) = h;
            *reinterpret_cast<uint2*>(smem + SM_B_LO + off) = l;
        }
    }
    __syncthreads();

    int cfg = wid >> 1;
    int T0  = reinterpret_cast<const int*>(smem + SM_T0)[cfg];
    int offs = (64 - T0) & 63;

    // ldmatrix lane roles
    int mrel  = (lane & 7) + ((lane >> 3) & 1) * 8;   // row within 16-tile
    int krel  = mrel;                                  // same decomposition for B
    int csel  = (lane >> 4) & 1;                       // chunk-pair selector

    float d[2][8][4];
    #pragma unroll
    for (int mt = 0; mt < 2; ++mt)
        #pragma unroll
        for (int nt = 0; nt < 8; ++nt)
            #pragma unroll
            for (int e = 0; e < 4; ++e) d[mt][nt][e] = 0.0f;

    // 3 passes: (Ahi,Bhi), (Alo,Bhi), (Ahi,Blo)
    #pragma unroll
    for (int pass = 0; pass < 3; ++pass) {
        uint32_t aBase = sbase + (pass == 1 ? SM_A_LO : SM_A_HI);
        uint32_t bBase = sbase + (pass == 2 ? SM_B_LO : SM_B_HI);

        #pragma unroll
        for (int kk = 0; kk < 4; ++kk) {
            // A fragments for both m-tiles
            uint32_t a[2][4];
            #pragma unroll
            for (int mt = 0; mt < 2; ++mt) {
                int mm = 32 * wid + 16 * mt + mrel;
                int chunk = kk * 2 + csel;
                uint32_t addr = aBase + (uint32_t)mm * 128 +
                                ((uint32_t)(chunk ^ (mm & 7)) << 4);
                ldsm_x4(a[mt][0], a[mt][1], a[mt][2], a[mt][3], addr);
            }
            // B fragments: 4 n-pairs, rolled row addressing
            int vphys = (kk * 16 + krel + T0) & 63;
            uint32_t brow = bBase + (uint32_t)vphys * 128;
            int vb = vphys & 7;
            #pragma unroll
            for (int np = 0; np < 4; ++np) {
                uint32_t b0, b1, b2, b3;
                int chunk = np * 2 + csel;
                ldsm_x4t(b0, b1, b2, b3, brow + ((uint32_t)(chunk ^ vb) << 4));
                #pragma unroll
                for (int mt = 0; mt < 2; ++mt) {
                    mma_bf16(d[mt][2 * np],     a[mt][0], a[mt][1], a[mt][2], a[mt][3], b0, b1);
                    mma_bf16(d[mt][2 * np + 1], a[mt][0], a[mt][1], a[mt][2], a[mt][3], b2, b3);
                }
            }
        }
    }

    // --- epilogue: +bias(j'), rolled scalar store ---
    const float* sb = reinterpret_cast<const float*>(smem + SM_BIAS);
    int qrow = lane >> 2;        // 0..7
    int qcol = (lane & 3) * 2;   // 0,2,4,6
    float* obase = out + (size_t)(i0 + cfg) * (NT * NX);

    #pragma unroll
    for (int mt = 0; mt < 2; ++mt) {
        int t0r = (32 * wid + 16 * mt + qrow) & 63;
        float* orow0 = obase + (size_t)t0r * NX;
        float* orow1 = obase + (size_t)(t0r + 8) * NX;
        #pragma unroll
        for (int nt = 0; nt < 8; ++nt) {
            int jp0 = 8 * nt + qcol;
            float bb0 = sb[jp0], bb1 = sb[jp0 + 1];
            int j0 = (jp0 + offs) & 63;
            int j1 = (jp0 + 1 + offs) & 63;
            orow0[j0] = d[mt][nt][0] + bb0;
            orow0[j1] = d[mt][nt][1] + bb1;
            orow1[j0] = d[mt][nt][2] + bb0;
            orow1[j1] = d[mt][nt][3] + bb1;
        }
    }
}

// ---------------------------------------------------------------------------
extern "C" void kernel_launch(void* const* d_in, const int* in_sizes, int n_in,
                              void* d_out, int out_size) {
    const float* phi = nullptr;
    const float* W   = nullptr;
    const float* b   = nullptr;
    for (int k = 0; k < n_in; ++k) {
        if      (in_sizes[k] == NCONF * NT * NX) phi = (const float*)d_in[k];
        else if (in_sizes[k] == NX * NX)         W   = (const float*)d_in[k];
        else if (in_sizes[k] == NX)              b   = (const float*)d_in[k];
    }
    float* out = (float*)d_out;
    int write_logdet = (out_size >= NCONF * NT * NX + NCONF) ? 1 : 0;

    cudaFuncSetAttribute(fused_kernel, cudaFuncAttributeMaxDynamicSharedMemorySize, SM_TOTAL);
    fused_kernel<<<NCONF / 2 + 1, 128, SM_TOTAL>>>(phi, W, b, out, write_logdet);
}

// round 6
// speedup vs baseline: 1.1053x; 1.1053x over previous
#include <cuda_runtime.h>
#include <cuda_bf16.h>
#include <math.h>
#include <stdint.h>

#define NCONF 8192
#define NT 64
#define NX 64

// Precomputed rolled-W fragment tables: [T0][kk][nt][lane] -> uint2 (b0,b1)
// b0 = bf16x2( W[(16kk+(l&3)*2   +T0)&63][n], W[(16kk+(l&3)*2+1 +T0)&63][n] )
// b1 = same with k+8,k+9 ;  n = 8*nt + (l>>2)
__device__ uint2 BhiV[64 * 4 * 8 * 32];
__device__ uint2 BloV[64 * 4 * 8 * 32];

static __device__ __forceinline__ uint32_t pack_hi2(float x, float y) {
    uint32_t r;
    asm("cvt.rn.bf16x2.f32 %0, %1, %2;" : "=r"(r) : "f"(y), "f"(x)); // lo16=bf16(x)
    return r;
}
// split: hi = bf16x2(x,y); lo = bf16x2 of residuals
static __device__ __forceinline__ void cvt_split(float x, float y,
                                                 uint32_t& hi, uint32_t& lo) {
    uint32_t h = pack_hi2(x, y);
    float hx = __uint_as_float(h << 16);
    float hy = __uint_as_float(h & 0xffff0000u);
    lo = pack_hi2(x - hx, y - hy);
    hi = h;
}

static __device__ __forceinline__ void mma_bf16(float* d, uint32_t a0, uint32_t a1,
                                                uint32_t a2, uint32_t a3,
                                                uint32_t b0, uint32_t b1) {
    asm volatile(
        "mma.sync.aligned.m16n8k16.row.col.f32.bf16.bf16.f32 "
        "{%0,%1,%2,%3}, {%4,%5,%6,%7}, {%8,%9}, {%0,%1,%2,%3};"
        : "+f"(d[0]), "+f"(d[1]), "+f"(d[2]), "+f"(d[3])
        : "r"(a0), "r"(a1), "r"(a2), "r"(a3), "r"(b0), "r"(b1));
}

// ---------------------------------------------------------------------------
// Prep kernel: 64 blocks, one rolled-W variant each (fragment-ordered bf16 hi/lo)
// ---------------------------------------------------------------------------
__global__ void __launch_bounds__(64) prep_kernel(const float* __restrict__ W) {
    int T0 = blockIdx.x;
    for (int idx = threadIdx.x; idx < 1024; idx += 64) {
        int lane = idx & 31;
        int nt   = (idx >> 5) & 7;
        int kk   = idx >> 8;
        int n    = 8 * nt + (lane >> 2);
        int k0   = 16 * kk + (lane & 3) * 2;
        float w00 = W[(((k0     + T0) & 63) << 6) + n];
        float w01 = W[(((k0 + 1 + T0) & 63) << 6) + n];
        float w10 = W[(((k0 + 8 + T0) & 63) << 6) + n];
        float w11 = W[(((k0 + 9 + T0) & 63) << 6) + n];
        uint32_t h0, l0, h1, l1;
        cvt_split(w00, w01, h0, l0);
        cvt_split(w10, w11, h1, l1);
        BhiV[T0 * 1024 + idx] = make_uint2(h0, h1);
        BloV[T0 * 1024 + idx] = make_uint2(l0, l1);
    }
}

// ---------------------------------------------------------------------------
// Main kernel: blocks 0..4095 -> 2 configs each (zero smem, zero syncthreads).
// Block 4096 -> LU(W) log|det| + logDet tail.
// ---------------------------------------------------------------------------
__global__ void __launch_bounds__(128, 4) main_kernel(
    const float* __restrict__ phi, const float* __restrict__ W,
    const float* __restrict__ b, float* __restrict__ out, int write_logdet)
{
    int tid  = threadIdx.x;
    int wid  = tid >> 5;
    int lane = tid & 31;

    if (blockIdx.x == NCONF / 2) {   // ---------------- LU block ----------------
        __shared__ float A[64][65];
        __shared__ float m[64];
        __shared__ float rv[2];
        __shared__ int   ri[2];
        __shared__ float sld;

        for (int idx = tid; idx < 64 * 64; idx += 128)
            A[idx >> 6][idx & 63] = W[idx];
        __syncthreads();

        float ld = 0.0f;
        for (int k = 0; k < 64; ++k) {
            if (tid < 64) {
                float v  = (tid >= k) ? fabsf(A[tid][k]) : -1.0f;
                int   vi = tid;
                #pragma unroll
                for (int off = 16; off > 0; off >>= 1) {
                    float ov = __shfl_down_sync(0xffffffffu, v,  off);
                    int   oi = __shfl_down_sync(0xffffffffu, vi, off);
                    if (ov > v) { v = ov; vi = oi; }
                }
                if ((tid & 31) == 0) { rv[tid >> 5] = v; ri[tid >> 5] = vi; }
            }
            __syncthreads();
            int p = (rv[1] > rv[0]) ? ri[1] : ri[0];
            if (tid < 64 && p != k) {
                float t1 = A[k][tid], t2 = A[p][tid];
                A[k][tid] = t2; A[p][tid] = t1;
            }
            __syncthreads();
            float piv = A[k][k];
            if (tid < 64) {
                ld += logf(fabsf(piv));
                if (tid > k) m[tid] = A[tid][k] / piv;
            }
            __syncthreads();
            if (tid < 64 && tid > k) {
                float akj = A[k][tid];
                for (int r = k + 1; r < 64; ++r)
                    A[r][tid] -= m[r] * akj;
            }
            __syncthreads();
        }
        if (write_logdet) {
            if (tid == 0) sld = ld;
            __syncthreads();
            float val = (float)NT * sld;
            float* tail = out + (size_t)NCONF * NT * NX;
            for (int idx = tid; idx < NCONF; idx += 128)
                tail[idx] = val;
        }
        return;
    }

    // ---------------- GEMM: warp w -> config i0 + (w>>1), t-rows 32*(w&1).. ----
    int i0   = blockIdx.x * 2;
    int cfg  = wid >> 1;
    int half = wid & 1;
    const float* phic = phi + (size_t)(i0 + cfg) * (NT * NX);

    // --- T0 (per-warp redundant, no smem) ---
    int T0;
    {
        const float* p = phic;
        float2 v0 = *reinterpret_cast<const float2*>(p + (size_t)lane * NX);
        float2 v1 = *reinterpret_cast<const float2*>(p + (size_t)(lane + 32) * NX);
        float b0 = fabsf(v0.x); int j0 = lane;
        float c0 = fabsf(v1.x);
        if (c0 < b0) { b0 = c0; j0 = lane + 32; }
        float b1 = fabsf(v0.y); int j1 = lane;
        float c1 = fabsf(v1.y);
        if (c1 < b1) { b1 = c1; j1 = lane + 32; }
        #pragma unroll
        for (int off = 16; off > 0; off >>= 1) {
            float ob = __shfl_xor_sync(0xffffffffu, b0, off);
            int   oj = __shfl_xor_sync(0xffffffffu, j0, off);
            if (ob < b0 || (ob == b0 && oj < j0)) { b0 = ob; j0 = oj; }
            ob = __shfl_xor_sync(0xffffffffu, b1, off);
            oj = __shfl_xor_sync(0xffffffffu, j1, off);
            if (ob < b1 || (ob == b1 && oj < j1)) { b1 = ob; j1 = oj; }
        }
        T0 = (j0 > j1) ? j1 : j0;           // same in all lanes (xor-reduce)
    }
    int offs = (64 - T0) & 63;

    // --- accumulators ---
    float d[2][8][4];
    #pragma unroll
    for (int mt = 0; mt < 2; ++mt)
        #pragma unroll
        for (int nt = 0; nt < 8; ++nt)
            #pragma unroll
            for (int e = 0; e < 4; ++e) d[mt][nt][e] = 0.0f;

    // per-lane A base: row = 32*half + (l>>2), col = (l&3)*2
    const float* aLane = phic + (size_t)(32 * half + (lane >> 2)) * NX + (lane & 3) * 2;
    const uint2* bhBase = BhiV + T0 * 1024 + lane;
    const uint2* blBase = BloV + T0 * 1024 + lane;

    #pragma unroll
    for (int kk = 0; kk < 4; ++kk) {
        // A fragments for both 16-row tiles, straight from gmem
        uint32_t ahi[2][4], alo[2][4];
        #pragma unroll
        for (int mt = 0; mt < 2; ++mt) {
            const float* p = aLane + (size_t)(16 * mt) * NX + 16 * kk;
            float2 v0 = *reinterpret_cast<const float2*>(p);             // a0
            float2 v1 = *reinterpret_cast<const float2*>(p + 8 * NX);    // a1 (+8 rows)
            float2 v2 = *reinterpret_cast<const float2*>(p + 8);         // a2 (+8 k)
            float2 v3 = *reinterpret_cast<const float2*>(p + 8 * NX + 8);// a3
            cvt_split(v0.x, v0.y, ahi[mt][0], alo[mt][0]);
            cvt_split(v1.x, v1.y, ahi[mt][1], alo[mt][1]);
            cvt_split(v2.x, v2.y, ahi[mt][2], alo[mt][2]);
            cvt_split(v3.x, v3.y, ahi[mt][3], alo[mt][3]);
        }
        const uint2* bh = bhBase + kk * 256;
        const uint2* bl = blBase + kk * 256;
        #pragma unroll
        for (int nt = 0; nt < 8; ++nt) {
            uint2 h = bh[nt * 32];
            uint2 l = bl[nt * 32];
            #pragma unroll
            for (int mt = 0; mt < 2; ++mt) {
                mma_bf16(d[mt][nt], ahi[mt][0], ahi[mt][1], ahi[mt][2], ahi[mt][3], h.x, h.y);
                mma_bf16(d[mt][nt], alo[mt][0], alo[mt][1], alo[mt][2], alo[mt][3], h.x, h.y);
                mma_bf16(d[mt][nt], ahi[mt][0], ahi[mt][1], ahi[mt][2], ahi[mt][3], l.x, l.y);
            }
        }
    }

    // --- epilogue: +bias(j'), rolled scalar stores ---
    int qrow = lane >> 2;
    int qcol = (lane & 3) * 2;
    float* obase = out + (size_t)(i0 + cfg) * (NT * NX);

    float2 bias[8];
    #pragma unroll
    for (int nt = 0; nt < 8; ++nt)
        bias[nt] = *reinterpret_cast<const float2*>(b + 8 * nt + qcol);

    #pragma unroll
    for (int mt = 0; mt < 2; ++mt) {
        int t0r = 32 * half + 16 * mt + qrow;
        float* orow0 = obase + (size_t)t0r * NX;
        float* orow1 = obase + (size_t)(t0r + 8) * NX;
        #pragma unroll
        for (int nt = 0; nt < 8; ++nt) {
            int jp0 = 8 * nt + qcol;
            int j0 = (jp0 + offs) & 63;
            int j1 = (jp0 + 1 + offs) & 63;
            orow0[j0] = d[mt][nt][0] + bias[nt].x;
            orow0[j1] = d[mt][nt][1] + bias[nt].y;
            orow1[j0] = d[mt][nt][2] + bias[nt].x;
            orow1[j1] = d[mt][nt][3] + bias[nt].y;
        }
    }
}

// ---------------------------------------------------------------------------
extern "C" void kernel_launch(void* const* d_in, const int* in_sizes, int n_in,
                              void* d_out, int out_size) {
    const float* phi = nullptr;
    const float* W   = nullptr;
    const float* b   = nullptr;
    for (int k = 0; k < n_in; ++k) {
        if      (in_sizes[k] == NCONF * NT * NX) phi = (const float*)d_in[k];
        else if (in_sizes[k] == NX * NX)         W   = (const float*)d_in[k];
        else if (in_sizes[k] == NX)              b   = (const float*)d_in[k];
    }
    float* out = (float*)d_out;
    int write_logdet = (out_size >= NCONF * NT * NX + NCONF) ? 1 : 0;

    prep_kernel<<<64, 64>>>(W);
    main_kernel<<<NCONF / 2 + 1, 128>>>(phi, W, b, out, write_logdet);
}